// round 15
// baseline (speedup 1.0000x reference)
#include <cuda_runtime.h>
#include <cuda_bf16.h>
#include <cstdint>
#include <cstddef>

#define NMAX 80000
#define EMAX 1000000
#define HD 128

// ---------------- scratch (static device globals) ----------------
__device__ __align__(16) float g_h[NMAX * HD];
__device__ __align__(16) float g_y[NMAX * HD];
__device__ __align__(16) float g_als[NMAX * 4];
__device__ __align__(16) float g_ald[NMAX * 4];
__device__ int g_rowptr[NMAX + 1];
__device__ int g_wptr[NMAX];
__device__ int g_csr[EMAX];
__device__ int g_bsums[256];
// transposed split weights: [slot][n*K + k], slots = {l0 gw, l0 fw, l1 gw, l1 fw, l2 gw, l2 fw}
__device__ __align__(16) __nv_bfloat16 g_wh[6][128 * 512];
__device__ __align__(16) __nv_bfloat16 g_wl[6][128 * 512];
// pre-split activations (hi/lo bf16), [row*K + k]
__device__ __align__(16) __nv_bfloat16 g_ah[NMAX * 512];
__device__ __align__(16) __nv_bfloat16 g_al[NMAX * 512];

__device__ __forceinline__ float lrelu(float v) { return v > 0.f ? v : 0.2f * v; }
__device__ __forceinline__ float comp4(float4 v, int i) {
    float r = v.x;
    if (i == 1) r = v.y; else if (i == 2) r = v.z; else if (i == 3) r = v.w;
    return r;
}

// ---------------- PTX helpers (all sm_80-baseline; valid on plain sm_103) ----------------
__device__ __forceinline__ uint32_t smem_u32(const void* p) {
    uint32_t a;
    asm("{ .reg .u64 t; cvta.to.shared.u64 t, %1; cvt.u32.u64 %0, t; }" : "=r"(a) : "l"(p));
    return a;
}
__device__ __forceinline__ void ldsm_x4(uint32_t* r, uint32_t addr) {
    asm volatile("ldmatrix.sync.aligned.m8n8.x4.shared.b16 {%0,%1,%2,%3}, [%4];"
        : "=r"(r[0]), "=r"(r[1]), "=r"(r[2]), "=r"(r[3]) : "r"(addr));
}
__device__ __forceinline__ void mma16816(float* d, const uint32_t* a, const uint32_t* b) {
    asm volatile("mma.sync.aligned.m16n8k16.row.col.f32.bf16.bf16.f32 "
        "{%0,%1,%2,%3}, {%4,%5,%6,%7}, {%8,%9}, {%0,%1,%2,%3};"
        : "+f"(d[0]), "+f"(d[1]), "+f"(d[2]), "+f"(d[3])
        : "r"(a[0]), "r"(a[1]), "r"(a[2]), "r"(a[3]), "r"(b[0]), "r"(b[1]));
}
__device__ __forceinline__ void cp16(uint32_t dst, const void* src) {
    asm volatile("cp.async.cg.shared.global [%0], [%1], 16;" :: "r"(dst), "l"(src));
}
#define CP_COMMIT() asm volatile("cp.async.commit_group;" ::: "memory")
template <int n>
__device__ __forceinline__ void cp_wait() {
    asm volatile("cp.async.wait_group %0;" :: "n"(n) : "memory");
}

__device__ __forceinline__ uint32_t split_pack(float a, float b, float& ra, float& rb) {
    __nv_bfloat16 ha = __float2bfloat16(a), hb = __float2bfloat16(b);
    ra = a - __bfloat162float(ha);
    rb = b - __bfloat162float(hb);
    return (uint32_t)__bfloat16_as_ushort(ha) | ((uint32_t)__bfloat16_as_ushort(hb) << 16);
}
__device__ __forceinline__ uint32_t pack_bf(float a, float b) {
    return (uint32_t)__bfloat16_as_ushort(__float2bfloat16(a))
         | ((uint32_t)__bfloat16_as_ushort(__float2bfloat16(b)) << 16);
}

// ---------------- CSR build (edge_index is int32) ----------------
__global__ void zero_deg_k(int N) {
    int i = blockIdx.x * blockDim.x + threadIdx.x;
    if (i < N) g_wptr[i] = 0;
}
__global__ void hist_k(const int* __restrict__ dst, int E, int N) {
    int i = blockIdx.x * blockDim.x + threadIdx.x;
    if (i < E) {
        unsigned d = (unsigned)dst[i];
        if (d < (unsigned)N) atomicAdd(&g_wptr[d], 1);
    }
}
__global__ void scan1_k(int n) {
    __shared__ int sm[1024];
    int i = blockIdx.x * 1024 + threadIdx.x;
    int v = (i < n) ? g_wptr[i] : 0;
    sm[threadIdx.x] = v;
    __syncthreads();
    for (int off = 1; off < 1024; off <<= 1) {
        int t = (threadIdx.x >= off) ? sm[threadIdx.x - off] : 0;
        __syncthreads();
        sm[threadIdx.x] += t;
        __syncthreads();
    }
    if (i < n) g_rowptr[i] = sm[threadIdx.x] - v;
    if (threadIdx.x == 1023) g_bsums[blockIdx.x] = sm[1023];
}
__global__ void scan2_k(int nb) {
    __shared__ int sm[256];
    int t = threadIdx.x;
    int v = (t < nb) ? g_bsums[t] : 0;
    sm[t] = v;
    __syncthreads();
    for (int off = 1; off < 256; off <<= 1) {
        int u = (t >= off) ? sm[t - off] : 0;
        __syncthreads();
        sm[t] += u;
        __syncthreads();
    }
    if (t < nb) g_bsums[t] = sm[t] - v;   // exclusive block sums
}
__global__ void scan3_k(int n, int E) {
    int i = blockIdx.x * 1024 + threadIdx.x;
    if (i < n) {
        int v = g_rowptr[i] + g_bsums[blockIdx.x];
        g_rowptr[i] = v;
        g_wptr[i] = v;
    }
    if (i == 0) g_rowptr[n] = E;
}
__global__ void scatter_k(const int* __restrict__ src, const int* __restrict__ dst, int E, int N) {
    int i = blockIdx.x * blockDim.x + threadIdx.x;
    if (i < E) {
        unsigned d = (unsigned)dst[i];
        unsigned s = (unsigned)src[i];
        if (d < (unsigned)N && s < (unsigned)N) {
            int pos = atomicAdd(&g_wptr[d], 1);
            if (pos < EMAX) g_csr[pos] = (int)s;
        }
    }
}

// ---------------- weight prep: two W[K,128] -> transposed split bf16 slots --------------
__global__ void wprep2_k(const float* __restrict__ Wa, const float* __restrict__ Wb,
                         int K, int slotA) {
    const float* W = (blockIdx.y == 0) ? Wa : Wb;
    int slot = slotA + blockIdx.y;
    int i = blockIdx.x * blockDim.x + threadIdx.x;
    if (i < K * 128) {
        int k = i >> 7, n = i & 127;
        float v = W[i];
        __nv_bfloat16 h = __float2bfloat16(v);
        __nv_bfloat16 l = __float2bfloat16(v - __bfloat162float(h));
        g_wh[slot][n * K + k] = h;
        g_wl[slot][n * K + k] = l;
    }
}

// ---------------- input split: fp32 x[N,512] -> g_ah / g_al bf16 ----------------
__global__ void asplit_k(const float* __restrict__ x, int total4) {
    int i = blockIdx.x * blockDim.x + threadIdx.x;
    if (i >= total4) return;
    float4 v = ((const float4*)x)[i];
    float r0, r1, r2, r3;
    uint32_t h0 = split_pack(v.x, v.y, r0, r1);
    uint32_t h1 = split_pack(v.z, v.w, r2, r3);
    ((uint2*)g_ah)[i] = make_uint2(h0, h1);
    ((uint2*)g_al)[i] = make_uint2(pack_bf(r0, r1), pack_bf(r2, r3));
}

// ---------------- fused dual GEMM: [g_h | g_y] = A @ [Wg | Wf], split-bf16 ---------------
// R13-proven kernel; single change: stage c+2 cp.async issued BEFORE the MMA phase.
#define LDS_B 80
#define ASTG 10240
#define BSTG 20480
#define STG_B (2 * ASTG + 2 * BSTG)
#define NSTAGE 3
__global__ void __launch_bounds__(512, 1) tcfused_k(
    int slot, int K, int N,
    const float* __restrict__ asrc, const float* __restrict__ adst,
    const float* __restrict__ fb, const float* __restrict__ fg,
    const float* __restrict__ fbeta, const float* __restrict__ gb)
{
    extern __shared__ __align__(16) char smem[];
    uint32_t sbase = smem_u32(smem);

    int tid = threadIdx.x, wid = tid >> 5, lane = tid & 31;
    const __nv_bfloat16* BgH = g_wh[slot];
    const __nv_bfloat16* BgL = g_wl[slot];
    const __nv_bfloat16* BfH = g_wh[slot + 1];
    const __nv_bfloat16* BfL = g_wl[slot + 1];

    size_t arow0 = (size_t)blockIdx.x * 128 * K;

    int m_warp = (wid >> 2) * 32;
    int nq = wid & 3;
    int n_warp = nq * 64;

    uint32_t a_off = (uint32_t)(lane & 15) * LDS_B + ((lane >> 4) << 4);
    uint32_t b_off = (uint32_t)((lane & 7) + ((lane >> 4) << 3)) * LDS_B + ((lane & 8) << 1);

    float acc[2][8][4];
#pragma unroll
    for (int mt = 0; mt < 2; mt++)
#pragma unroll
        for (int nt = 0; nt < 8; nt++)
#pragma unroll
            for (int r = 0; r < 4; r++) acc[mt][nt][r] = 0.f;

    int lrow = tid >> 2, ls4 = tid & 3;
    auto load_stage = [&](int st, int k0) {
        uint32_t sb = sbase + st * STG_B;
        uint32_t dof = (uint32_t)lrow * LDS_B + ls4 * 16;
        size_t aoff = arow0 + (size_t)lrow * K + k0 + ls4 * 8;
        size_t boff = (size_t)lrow * K + k0 + ls4 * 8;
        cp16(sb + dof, g_ah + aoff);
        cp16(sb + ASTG + dof, g_al + aoff);
        uint32_t dof2 = dof + 128 * LDS_B;
        cp16(sb + 2 * ASTG + dof, BgH + boff);
        cp16(sb + 2 * ASTG + BSTG + dof, BgL + boff);
        cp16(sb + 2 * ASTG + dof2, BfH + boff);
        cp16(sb + 2 * ASTG + BSTG + dof2, BfL + boff);
    };

    int nchunk = K >> 5;
    load_stage(0, 0);
    CP_COMMIT();
    if (nchunk > 1) { load_stage(1, 32); CP_COMMIT(); }

    for (int c = 0; c < nchunk; c++) {
        if (c + 1 < nchunk) cp_wait<1>(); else cp_wait<0>();
        __syncthreads();

        // hoisted: issue stage c+2 loads BEFORE the MMA phase so LDGSTS overlaps compute
        if (c + 2 < nchunk) {
            load_stage((c + 2) % NSTAGE, (c + 2) * 32);
            CP_COMMIT();
        }

        uint32_t stb = sbase + (c % NSTAGE) * STG_B;
        uint32_t pAh = stb + a_off, pAl = stb + ASTG + a_off;
        uint32_t pBh = stb + 2 * ASTG + b_off, pBl = stb + 2 * ASTG + BSTG + b_off;

#pragma unroll
        for (int ks = 0; ks < 2; ks++) {
            uint32_t ksb = ks * 32;
            uint32_t ah[2][4], al_[2][4];
#pragma unroll
            for (int mt = 0; mt < 2; mt++) {
                uint32_t ro = (uint32_t)(m_warp + mt * 16) * LDS_B + ksb;
                ldsm_x4(ah[mt], pAh + ro);
                ldsm_x4(al_[mt], pAl + ro);
            }
#pragma unroll
            for (int p = 0; p < 4; p++) {
                uint32_t ro = (uint32_t)(n_warp + p * 16) * LDS_B + ksb;
                uint32_t tb0[4], tb1[4];
                ldsm_x4(tb0, pBh + ro);
                ldsm_x4(tb1, pBl + ro);
#pragma unroll
                for (int mt = 0; mt < 2; mt++) {
                    mma16816(acc[mt][2 * p + 0], ah[mt], tb0 + 0);
                    mma16816(acc[mt][2 * p + 0], ah[mt], tb1 + 0);
                    mma16816(acc[mt][2 * p + 0], al_[mt], tb0 + 0);
                    mma16816(acc[mt][2 * p + 1], ah[mt], tb0 + 2);
                    mma16816(acc[mt][2 * p + 1], ah[mt], tb1 + 2);
                    mma16816(acc[mt][2 * p + 1], al_[mt], tb0 + 2);
                }
            }
        }
    }

    int gid = lane >> 2, tig = lane & 3;
    const float bns = rsqrtf(1.f + 1e-5f);
    if (nq < 2) {
        int headbase = nq * 2;
#pragma unroll
        for (int mt = 0; mt < 2; mt++) {
            int row0 = blockIdx.x * 128 + m_warp + mt * 16 + gid;
            float sA0 = 0.f, sB0 = 0.f, dA0 = 0.f, dB0 = 0.f;
            float sA8 = 0.f, sB8 = 0.f, dA8 = 0.f, dB8 = 0.f;
#pragma unroll
            for (int nt = 0; nt < 8; nt++) {
                int col = n_warp + nt * 8 + tig * 2;
                float v0 = acc[mt][nt][0], v1 = acc[mt][nt][1];
                float v2 = acc[mt][nt][2], v3 = acc[mt][nt][3];
                if (row0 < N)     *(float2*)(g_h + (size_t)row0 * 128 + col) = make_float2(v0, v1);
                if (row0 + 8 < N) *(float2*)(g_h + (size_t)(row0 + 8) * 128 + col) = make_float2(v2, v3);
                float wa0 = asrc[col], wa1 = asrc[col + 1];
                float wd0 = adst[col], wd1 = adst[col + 1];
                float c0 = v0 * wa0 + v1 * wa1, c8 = v2 * wa0 + v3 * wa1;
                float e0 = v0 * wd0 + v1 * wd1, e8 = v2 * wd0 + v3 * wd1;
                if (nt < 4) { sA0 += c0; sA8 += c8; dA0 += e0; dA8 += e8; }
                else        { sB0 += c0; sB8 += c8; dB0 += e0; dB8 += e8; }
            }
#define QR(v) v += __shfl_xor_sync(0xffffffffu, v, 1); v += __shfl_xor_sync(0xffffffffu, v, 2);
            QR(sA0) QR(sB0) QR(dA0) QR(dB0) QR(sA8) QR(sB8) QR(dA8) QR(dB8)
#undef QR
            if (tig == 0) {
                if (row0 < N) {
                    g_als[row0 * 4 + headbase] = sA0;
                    g_als[row0 * 4 + headbase + 1] = sB0;
                    g_ald[row0 * 4 + headbase] = dA0;
                    g_ald[row0 * 4 + headbase + 1] = dB0;
                }
                if (row0 + 8 < N) {
                    g_als[(row0 + 8) * 4 + headbase] = sA8;
                    g_als[(row0 + 8) * 4 + headbase + 1] = sB8;
                    g_ald[(row0 + 8) * 4 + headbase] = dA8;
                    g_ald[(row0 + 8) * 4 + headbase + 1] = dB8;
                }
            }
        }
    } else {
#pragma unroll
        for (int mt = 0; mt < 2; mt++) {
            int row0 = blockIdx.x * 128 + m_warp + mt * 16 + gid;
#pragma unroll
            for (int nt = 0; nt < 8; nt++) {
                int col = (n_warp - 128) + nt * 8 + tig * 2;
                float v0 = acc[mt][nt][0], v1 = acc[mt][nt][1];
                float v2 = acc[mt][nt][2], v3 = acc[mt][nt][3];
                float s0 = fg[col] * bns, s1 = fg[col + 1] * bns;
                float b0 = fb[col], b1 = fb[col + 1];
                float t0 = fbeta[col], t1 = fbeta[col + 1];
                float g0 = gb[col], g1 = gb[col + 1];
                v0 = fmaxf((v0 + b0) * s0 + t0, 0.f) + g0;
                v1 = fmaxf((v1 + b1) * s1 + t1, 0.f) + g1;
                v2 = fmaxf((v2 + b0) * s0 + t0, 0.f) + g0;
                v3 = fmaxf((v3 + b1) * s1 + t1, 0.f) + g1;
                if (row0 < N)     *(float2*)(g_y + (size_t)row0 * 128 + col) = make_float2(v0, v1);
                if (row0 + 8 < N) *(float2*)(g_y + (size_t)(row0 + 8) * 128 + col) = make_float2(v2, v3);
            }
        }
    }
}

// ---------------- single-pass flash-style softmax + aggregation (warp per node) ----------
// OUTMODE 0: write split bf16 (g_ah/g_al, K=128).  OUTMODE 1: fused classifier -> out.
template <int OUTMODE>
__global__ void agg_k(int N, const float* __restrict__ cw, const float* __restrict__ cb,
                      float* __restrict__ out)
{
    int n = (blockIdx.x * blockDim.x + threadIdx.x) >> 5;
    int lane = threadIdx.x & 31;
    if (n >= N) return;
    int head = lane >> 3;
    float myald = comp4(((const float4*)g_ald)[n], head);
    float eself = lrelu(comp4(((const float4*)g_als)[n], head) + myald);

    const float4* h4 = (const float4*)g_h;

    float m = eself, s = 1.f;
    float4 acc = h4[(size_t)n * 32 + lane];

    int beg = g_rowptr[n], end = g_rowptr[n + 1];
    int i = beg;
    for (; i + 4 <= end; i += 4) {
        int s0 = g_csr[i], s1 = g_csr[i + 1], s2 = g_csr[i + 2], s3 = g_csr[i + 3];
        float4 hv0 = h4[(size_t)s0 * 32 + lane];
        float4 hv1 = h4[(size_t)s1 * 32 + lane];
        float4 hv2 = h4[(size_t)s2 * 32 + lane];
        float4 hv3 = h4[(size_t)s3 * 32 + lane];
        float e0 = lrelu(g_als[s0 * 4 + head] + myald);
        float e1 = lrelu(g_als[s1 * 4 + head] + myald);
        float e2 = lrelu(g_als[s2 * 4 + head] + myald);
        float e3 = lrelu(g_als[s3 * 4 + head] + myald);
        float mx = fmaxf(fmaxf(e0, e1), fmaxf(e2, e3));
        if (mx > m) {
            float r = __expf(m - mx);
            s *= r;
            acc.x *= r; acc.y *= r; acc.z *= r; acc.w *= r;
            m = mx;
        }
        float p0 = __expf(e0 - m), p1 = __expf(e1 - m);
        float p2 = __expf(e2 - m), p3 = __expf(e3 - m);
        s += p0 + p1 + p2 + p3;
        acc.x += p0 * hv0.x + p1 * hv1.x + p2 * hv2.x + p3 * hv3.x;
        acc.y += p0 * hv0.y + p1 * hv1.y + p2 * hv2.y + p3 * hv3.y;
        acc.z += p0 * hv0.z + p1 * hv1.z + p2 * hv2.z + p3 * hv3.z;
        acc.w += p0 * hv0.w + p1 * hv1.w + p2 * hv2.w + p3 * hv3.w;
    }
    for (; i < end; i++) {
        int si = g_csr[i];
        float4 hv = h4[(size_t)si * 32 + lane];
        float e = lrelu(g_als[si * 4 + head] + myald);
        if (e > m) {
            float r = __expf(m - e);
            s *= r;
            acc.x *= r; acc.y *= r; acc.z *= r; acc.w *= r;
            m = e;
        }
        float p = __expf(e - m);
        s += p;
        acc.x += p * hv.x; acc.y += p * hv.y;
        acc.z += p * hv.z; acc.w += p * hv.w;
    }

    float inv = 1.f / s;
    float4 yv = ((const float4*)g_y)[(size_t)n * 32 + lane];
    float4 o4;
    o4.x = fmaxf(acc.x * inv + yv.x, 0.f);
    o4.y = fmaxf(acc.y * inv + yv.y, 0.f);
    o4.z = fmaxf(acc.z * inv + yv.z, 0.f);
    o4.w = fmaxf(acc.w * inv + yv.w, 0.f);

    if (OUTMODE == 0) {
        float r0, r1, r2, r3;
        uint32_t h0 = split_pack(o4.x, o4.y, r0, r1);
        uint32_t h1 = split_pack(o4.z, o4.w, r2, r3);
        ((uint2*)g_ah)[(size_t)n * 32 + lane] = make_uint2(h0, h1);
        ((uint2*)g_al)[(size_t)n * 32 + lane] = make_uint2(pack_bf(r0, r1), pack_bf(r2, r3));
    } else {
        int k0 = lane * 4;
#pragma unroll
        for (int o = 0; o < 10; o++) {
            float p = o4.x * cw[(k0 + 0) * 10 + o] + o4.y * cw[(k0 + 1) * 10 + o]
                    + o4.z * cw[(k0 + 2) * 10 + o] + o4.w * cw[(k0 + 3) * 10 + o];
#pragma unroll
            for (int off = 16; off; off >>= 1) p += __shfl_xor_sync(0xffffffffu, p, off);
            if (lane == 0) out[(size_t)n * 10 + o] = p + cb[o];
        }
    }
}

// ---------------- host ----------------
static const int TCF_SMEM = NSTAGE * STG_B;   // 184320 bytes

struct HxStreams {
    cudaStream_t s2 = 0;
    cudaEvent_t e1 = 0, e2 = 0, e3 = 0;
    bool ok = false;
    HxStreams() {
        ok = (cudaStreamCreateWithFlags(&s2, cudaStreamNonBlocking) == cudaSuccess)
          && (cudaEventCreateWithFlags(&e1, cudaEventDisableTiming) == cudaSuccess)
          && (cudaEventCreateWithFlags(&e2, cudaEventDisableTiming) == cudaSuccess)
          && (cudaEventCreateWithFlags(&e3, cudaEventDisableTiming) == cudaSuccess);
    }
};
static HxStreams hx;

extern "C" void kernel_launch(void* const* d_in, const int* in_sizes, int n_in,
                              void* d_out, int out_size)
{
    const float* x = (const float*)d_in[0];
    const int* ei = (const int*)d_in[1];
    int N = in_sizes[0] / 512;
    int E = in_sizes[1] / 2;
    const int* src = ei;
    const int* dst = ei + E;

    const float* gw[3]    = {(const float*)d_in[3],  (const float*)d_in[11], (const float*)d_in[19]};
    const float* gas[3]   = {(const float*)d_in[4],  (const float*)d_in[12], (const float*)d_in[20]};
    const float* gad[3]   = {(const float*)d_in[5],  (const float*)d_in[13], (const float*)d_in[21]};
    const float* gbp[3]   = {(const float*)d_in[6],  (const float*)d_in[14], (const float*)d_in[22]};
    const float* fw[3]    = {(const float*)d_in[7],  (const float*)d_in[15], (const float*)d_in[23]};
    const float* fbp[3]   = {(const float*)d_in[8],  (const float*)d_in[16], (const float*)d_in[24]};
    const float* fgp[3]   = {(const float*)d_in[9],  (const float*)d_in[17], (const float*)d_in[25]};
    const float* fbeta[3] = {(const float*)d_in[10], (const float*)d_in[18], (const float*)d_in[26]};
    const float* cw = (const float*)d_in[27];
    const float* cb = (const float*)d_in[28];

    cudaFuncSetAttribute(tcfused_k, cudaFuncAttributeMaxDynamicSharedMemorySize, TCF_SMEM);

    int nb = (N + 1023) / 1024;
    int gemmBlocks = (N + 127) / 128;
    int warpBlocks = (N * 32 + 255) / 256;

    bool fork = hx.ok;
    cudaStream_t sB = fork ? hx.s2 : (cudaStream_t)0;

    if (fork) {
        cudaEventRecord(hx.e1, 0);
        cudaStreamWaitEvent(hx.s2, hx.e1, 0);
    }

    // side stream: layer-0 weight prep FIRST (so it overlaps asplit), then CSR + l1/l2 prep
    wprep2_k<<<dim3(256, 2), 256, 0, sB>>>(gw[0], fw[0], 512, 0);
    if (fork) cudaEventRecord(hx.e3, hx.s2);
    zero_deg_k<<<(N + 255) / 256, 256, 0, sB>>>(N);
    hist_k<<<(E + 255) / 256, 256, 0, sB>>>(dst, E, N);
    scan1_k<<<nb, 1024, 0, sB>>>(N);
    scan2_k<<<1, 256, 0, sB>>>(nb);
    scan3_k<<<nb, 1024, 0, sB>>>(N, E);
    scatter_k<<<(E + 255) / 256, 256, 0, sB>>>(src, dst, E, N);
    wprep2_k<<<dim3(64, 2), 256, 0, sB>>>(gw[1], fw[1], 128, 2);
    wprep2_k<<<dim3(64, 2), 256, 0, sB>>>(gw[2], fw[2], 128, 4);

    // main stream: input split (overlaps wprep0), then layer-0 fused GEMM
    asplit_k<<<(N * 512 / 4 + 255) / 256, 256>>>(x, N * 512 / 4);
    if (fork) cudaStreamWaitEvent(0, hx.e3, 0);
    tcfused_k<<<gemmBlocks, 512, TCF_SMEM>>>(0, 512, N, gas[0], gad[0], fbp[0], fgp[0], fbeta[0], gbp[0]);

    if (fork) {
        cudaEventRecord(hx.e2, hx.s2);
        cudaStreamWaitEvent(0, hx.e2, 0);
    }

    // layer 0 aggregation -> split activations for layer 1
    agg_k<0><<<warpBlocks, 256>>>(N, nullptr, nullptr, nullptr);

    // layer 1 (K=128)
    tcfused_k<<<gemmBlocks, 512, TCF_SMEM>>>(2, 128, N, gas[1], gad[1], fbp[1], fgp[1], fbeta[1], gbp[1]);
    agg_k<0><<<warpBlocks, 256>>>(N, nullptr, nullptr, nullptr);

    // layer 2 (K=128), final agg fuses the classifier
    tcfused_k<<<gemmBlocks, 512, TCF_SMEM>>>(4, 128, N, gas[2], gad[2], fbp[2], fgp[2], fbeta[2], gbp[2]);
    agg_k<1><<<warpBlocks, 256>>>(N, cw, cb, (float*)d_out);
}

// round 16
// speedup vs baseline: 1.0684x; 1.0684x over previous
#include <cuda_runtime.h>
#include <cuda_bf16.h>
#include <cstdint>
#include <cstddef>

#define NMAX 80000
#define EMAX 1000000
#define HD 128

// ---------------- scratch (static device globals) ----------------
__device__ __align__(16) float g_h[NMAX * HD];
__device__ __align__(16) float g_y[NMAX * HD];
__device__ __align__(16) float g_als[NMAX * 4];
__device__ __align__(16) float g_ald[NMAX * 4];
__device__ int g_rowptr[NMAX + 1];
__device__ int g_wptr[NMAX];
__device__ int g_csr[EMAX];
__device__ int g_bsums[256];
// transposed split weights: [slot][n*K + k], slots = {l0 gw, l0 fw, l1 gw, l1 fw, l2 gw, l2 fw}
__device__ __align__(16) __nv_bfloat16 g_wh[6][128 * 512];
__device__ __align__(16) __nv_bfloat16 g_wl[6][128 * 512];
// pre-split activations (hi/lo bf16), [row*K + k]
__device__ __align__(16) __nv_bfloat16 g_ah[NMAX * 512];
__device__ __align__(16) __nv_bfloat16 g_al[NMAX * 512];

__device__ __forceinline__ float lrelu(float v) { return v > 0.f ? v : 0.2f * v; }
__device__ __forceinline__ float comp4(float4 v, int i) {
    float r = v.x;
    if (i == 1) r = v.y; else if (i == 2) r = v.z; else if (i == 3) r = v.w;
    return r;
}

// ---------------- PTX helpers (all sm_80-baseline; valid on plain sm_103) ----------------
__device__ __forceinline__ uint32_t smem_u32(const void* p) {
    uint32_t a;
    asm("{ .reg .u64 t; cvta.to.shared.u64 t, %1; cvt.u32.u64 %0, t; }" : "=r"(a) : "l"(p));
    return a;
}
__device__ __forceinline__ void ldsm_x4(uint32_t* r, uint32_t addr) {
    asm volatile("ldmatrix.sync.aligned.m8n8.x4.shared.b16 {%0,%1,%2,%3}, [%4];"
        : "=r"(r[0]), "=r"(r[1]), "=r"(r[2]), "=r"(r[3]) : "r"(addr));
}
__device__ __forceinline__ void mma16816(float* d, const uint32_t* a, const uint32_t* b) {
    asm volatile("mma.sync.aligned.m16n8k16.row.col.f32.bf16.bf16.f32 "
        "{%0,%1,%2,%3}, {%4,%5,%6,%7}, {%8,%9}, {%0,%1,%2,%3};"
        : "+f"(d[0]), "+f"(d[1]), "+f"(d[2]), "+f"(d[3])
        : "r"(a[0]), "r"(a[1]), "r"(a[2]), "r"(a[3]), "r"(b[0]), "r"(b[1]));
}
__device__ __forceinline__ void cp16(uint32_t dst, const void* src) {
    asm volatile("cp.async.cg.shared.global [%0], [%1], 16;" :: "r"(dst), "l"(src));
}
#define CP_COMMIT() asm volatile("cp.async.commit_group;" ::: "memory")
template <int n>
__device__ __forceinline__ void cp_wait() {
    asm volatile("cp.async.wait_group %0;" :: "n"(n) : "memory");
}

__device__ __forceinline__ uint32_t split_pack(float a, float b, float& ra, float& rb) {
    __nv_bfloat16 ha = __float2bfloat16(a), hb = __float2bfloat16(b);
    ra = a - __bfloat162float(ha);
    rb = b - __bfloat162float(hb);
    return (uint32_t)__bfloat16_as_ushort(ha) | ((uint32_t)__bfloat16_as_ushort(hb) << 16);
}
__device__ __forceinline__ uint32_t pack_bf(float a, float b) {
    return (uint32_t)__bfloat16_as_ushort(__float2bfloat16(a))
         | ((uint32_t)__bfloat16_as_ushort(__float2bfloat16(b)) << 16);
}

// ---------------- CSR build (edge_index is int32) ----------------
__global__ void zero_deg_k(int N) {
    int i = blockIdx.x * blockDim.x + threadIdx.x;
    if (i < N) g_wptr[i] = 0;
}
__global__ void hist_k(const int* __restrict__ dst, int E, int N) {
    int i = blockIdx.x * blockDim.x + threadIdx.x;
    if (i < E) {
        unsigned d = (unsigned)dst[i];
        if (d < (unsigned)N) atomicAdd(&g_wptr[d], 1);
    }
}
__global__ void scan1_k(int n) {
    __shared__ int sm[1024];
    int i = blockIdx.x * 1024 + threadIdx.x;
    int v = (i < n) ? g_wptr[i] : 0;
    sm[threadIdx.x] = v;
    __syncthreads();
    for (int off = 1; off < 1024; off <<= 1) {
        int t = (threadIdx.x >= off) ? sm[threadIdx.x - off] : 0;
        __syncthreads();
        sm[threadIdx.x] += t;
        __syncthreads();
    }
    if (i < n) g_rowptr[i] = sm[threadIdx.x] - v;
    if (threadIdx.x == 1023) g_bsums[blockIdx.x] = sm[1023];
}
__global__ void scan2_k(int nb) {
    __shared__ int sm[256];
    int t = threadIdx.x;
    int v = (t < nb) ? g_bsums[t] : 0;
    sm[t] = v;
    __syncthreads();
    for (int off = 1; off < 256; off <<= 1) {
        int u = (t >= off) ? sm[t - off] : 0;
        __syncthreads();
        sm[t] += u;
        __syncthreads();
    }
    if (t < nb) g_bsums[t] = sm[t] - v;   // exclusive block sums
}
__global__ void scan3_k(int n, int E) {
    int i = blockIdx.x * 1024 + threadIdx.x;
    if (i < n) {
        int v = g_rowptr[i] + g_bsums[blockIdx.x];
        g_rowptr[i] = v;
        g_wptr[i] = v;
    }
    if (i == 0) g_rowptr[n] = E;
}
__global__ void scatter_k(const int* __restrict__ src, const int* __restrict__ dst, int E, int N) {
    int i = blockIdx.x * blockDim.x + threadIdx.x;
    if (i < E) {
        unsigned d = (unsigned)dst[i];
        unsigned s = (unsigned)src[i];
        if (d < (unsigned)N && s < (unsigned)N) {
            int pos = atomicAdd(&g_wptr[d], 1);
            if (pos < EMAX) g_csr[pos] = (int)s;
        }
    }
}

// ---------------- weight prep: two W[K,128] -> transposed split bf16 slots --------------
__global__ void wprep2_k(const float* __restrict__ Wa, const float* __restrict__ Wb,
                         int K, int slotA) {
    const float* W = (blockIdx.y == 0) ? Wa : Wb;
    int slot = slotA + blockIdx.y;
    int i = blockIdx.x * blockDim.x + threadIdx.x;
    if (i < K * 128) {
        int k = i >> 7, n = i & 127;
        float v = W[i];
        __nv_bfloat16 h = __float2bfloat16(v);
        __nv_bfloat16 l = __float2bfloat16(v - __bfloat162float(h));
        g_wh[slot][n * K + k] = h;
        g_wl[slot][n * K + k] = l;
    }
}

// ---------------- input split: fp32 x[N,512] -> g_ah / g_al bf16 ----------------
__global__ void asplit_k(const float* __restrict__ x, int total4) {
    int i = blockIdx.x * blockDim.x + threadIdx.x;
    if (i >= total4) return;
    float4 v = ((const float4*)x)[i];
    float r0, r1, r2, r3;
    uint32_t h0 = split_pack(v.x, v.y, r0, r1);
    uint32_t h1 = split_pack(v.z, v.w, r2, r3);
    ((uint2*)g_ah)[i] = make_uint2(h0, h1);
    ((uint2*)g_al)[i] = make_uint2(pack_bf(r0, r1), pack_bf(r2, r3));
}

// ---------------- fused dual GEMM: [g_h | g_y] = A @ [Wg | Wf], split-bf16 ---------------
// R13-proven kernel, byte-identical: stage c+2 cp.async issued AFTER the MMA phase.
#define LDS_B 80
#define ASTG 10240
#define BSTG 20480
#define STG_B (2 * ASTG + 2 * BSTG)
#define NSTAGE 3
__global__ void __launch_bounds__(512, 1) tcfused_k(
    int slot, int K, int N,
    const float* __restrict__ asrc, const float* __restrict__ adst,
    const float* __restrict__ fb, const float* __restrict__ fg,
    const float* __restrict__ fbeta, const float* __restrict__ gb)
{
    extern __shared__ __align__(16) char smem[];
    uint32_t sbase = smem_u32(smem);

    int tid = threadIdx.x, wid = tid >> 5, lane = tid & 31;
    const __nv_bfloat16* BgH = g_wh[slot];
    const __nv_bfloat16* BgL = g_wl[slot];
    const __nv_bfloat16* BfH = g_wh[slot + 1];
    const __nv_bfloat16* BfL = g_wl[slot + 1];

    size_t arow0 = (size_t)blockIdx.x * 128 * K;

    int m_warp = (wid >> 2) * 32;
    int nq = wid & 3;
    int n_warp = nq * 64;

    uint32_t a_off = (uint32_t)(lane & 15) * LDS_B + ((lane >> 4) << 4);
    uint32_t b_off = (uint32_t)((lane & 7) + ((lane >> 4) << 3)) * LDS_B + ((lane & 8) << 1);

    float acc[2][8][4];
#pragma unroll
    for (int mt = 0; mt < 2; mt++)
#pragma unroll
        for (int nt = 0; nt < 8; nt++)
#pragma unroll
            for (int r = 0; r < 4; r++) acc[mt][nt][r] = 0.f;

    int lrow = tid >> 2, ls4 = tid & 3;
    auto load_stage = [&](int st, int k0) {
        uint32_t sb = sbase + st * STG_B;
        uint32_t dof = (uint32_t)lrow * LDS_B + ls4 * 16;
        size_t aoff = arow0 + (size_t)lrow * K + k0 + ls4 * 8;
        size_t boff = (size_t)lrow * K + k0 + ls4 * 8;
        cp16(sb + dof, g_ah + aoff);
        cp16(sb + ASTG + dof, g_al + aoff);
        uint32_t dof2 = dof + 128 * LDS_B;
        cp16(sb + 2 * ASTG + dof, BgH + boff);
        cp16(sb + 2 * ASTG + BSTG + dof, BgL + boff);
        cp16(sb + 2 * ASTG + dof2, BfH + boff);
        cp16(sb + 2 * ASTG + BSTG + dof2, BfL + boff);
    };

    int nchunk = K >> 5;
    load_stage(0, 0);
    CP_COMMIT();
    if (nchunk > 1) { load_stage(1, 32); CP_COMMIT(); }

    for (int c = 0; c < nchunk; c++) {
        if (c + 1 < nchunk) cp_wait<1>(); else cp_wait<0>();
        __syncthreads();

        uint32_t stb = sbase + (c % NSTAGE) * STG_B;
        uint32_t pAh = stb + a_off, pAl = stb + ASTG + a_off;
        uint32_t pBh = stb + 2 * ASTG + b_off, pBl = stb + 2 * ASTG + BSTG + b_off;

#pragma unroll
        for (int ks = 0; ks < 2; ks++) {
            uint32_t ksb = ks * 32;
            uint32_t ah[2][4], al_[2][4];
#pragma unroll
            for (int mt = 0; mt < 2; mt++) {
                uint32_t ro = (uint32_t)(m_warp + mt * 16) * LDS_B + ksb;
                ldsm_x4(ah[mt], pAh + ro);
                ldsm_x4(al_[mt], pAl + ro);
            }
#pragma unroll
            for (int p = 0; p < 4; p++) {
                uint32_t ro = (uint32_t)(n_warp + p * 16) * LDS_B + ksb;
                uint32_t tb0[4], tb1[4];
                ldsm_x4(tb0, pBh + ro);
                ldsm_x4(tb1, pBl + ro);
#pragma unroll
                for (int mt = 0; mt < 2; mt++) {
                    mma16816(acc[mt][2 * p + 0], ah[mt], tb0 + 0);
                    mma16816(acc[mt][2 * p + 0], ah[mt], tb1 + 0);
                    mma16816(acc[mt][2 * p + 0], al_[mt], tb0 + 0);
                    mma16816(acc[mt][2 * p + 1], ah[mt], tb0 + 2);
                    mma16816(acc[mt][2 * p + 1], ah[mt], tb1 + 2);
                    mma16816(acc[mt][2 * p + 1], al_[mt], tb0 + 2);
                }
            }
        }
        if (c + 2 < nchunk) {
            load_stage((c + 2) % NSTAGE, (c + 2) * 32);
            CP_COMMIT();
        }
    }

    int gid = lane >> 2, tig = lane & 3;
    const float bns = rsqrtf(1.f + 1e-5f);
    if (nq < 2) {
        int headbase = nq * 2;
#pragma unroll
        for (int mt = 0; mt < 2; mt++) {
            int row0 = blockIdx.x * 128 + m_warp + mt * 16 + gid;
            float sA0 = 0.f, sB0 = 0.f, dA0 = 0.f, dB0 = 0.f;
            float sA8 = 0.f, sB8 = 0.f, dA8 = 0.f, dB8 = 0.f;
#pragma unroll
            for (int nt = 0; nt < 8; nt++) {
                int col = n_warp + nt * 8 + tig * 2;
                float v0 = acc[mt][nt][0], v1 = acc[mt][nt][1];
                float v2 = acc[mt][nt][2], v3 = acc[mt][nt][3];
                if (row0 < N)     *(float2*)(g_h + (size_t)row0 * 128 + col) = make_float2(v0, v1);
                if (row0 + 8 < N) *(float2*)(g_h + (size_t)(row0 + 8) * 128 + col) = make_float2(v2, v3);
                float wa0 = asrc[col], wa1 = asrc[col + 1];
                float wd0 = adst[col], wd1 = adst[col + 1];
                float c0 = v0 * wa0 + v1 * wa1, c8 = v2 * wa0 + v3 * wa1;
                float e0 = v0 * wd0 + v1 * wd1, e8 = v2 * wd0 + v3 * wd1;
                if (nt < 4) { sA0 += c0; sA8 += c8; dA0 += e0; dA8 += e8; }
                else        { sB0 += c0; sB8 += c8; dB0 += e0; dB8 += e8; }
            }
#define QR(v) v += __shfl_xor_sync(0xffffffffu, v, 1); v += __shfl_xor_sync(0xffffffffu, v, 2);
            QR(sA0) QR(sB0) QR(dA0) QR(dB0) QR(sA8) QR(sB8) QR(dA8) QR(dB8)
#undef QR
            if (tig == 0) {
                if (row0 < N) {
                    g_als[row0 * 4 + headbase] = sA0;
                    g_als[row0 * 4 + headbase + 1] = sB0;
                    g_ald[row0 * 4 + headbase] = dA0;
                    g_ald[row0 * 4 + headbase + 1] = dB0;
                }
                if (row0 + 8 < N) {
                    g_als[(row0 + 8) * 4 + headbase] = sA8;
                    g_als[(row0 + 8) * 4 + headbase + 1] = sB8;
                    g_ald[(row0 + 8) * 4 + headbase] = dA8;
                    g_ald[(row0 + 8) * 4 + headbase + 1] = dB8;
                }
            }
        }
    } else {
#pragma unroll
        for (int mt = 0; mt < 2; mt++) {
            int row0 = blockIdx.x * 128 + m_warp + mt * 16 + gid;
#pragma unroll
            for (int nt = 0; nt < 8; nt++) {
                int col = (n_warp - 128) + nt * 8 + tig * 2;
                float v0 = acc[mt][nt][0], v1 = acc[mt][nt][1];
                float v2 = acc[mt][nt][2], v3 = acc[mt][nt][3];
                float s0 = fg[col] * bns, s1 = fg[col + 1] * bns;
                float b0 = fb[col], b1 = fb[col + 1];
                float t0 = fbeta[col], t1 = fbeta[col + 1];
                float g0 = gb[col], g1 = gb[col + 1];
                v0 = fmaxf((v0 + b0) * s0 + t0, 0.f) + g0;
                v1 = fmaxf((v1 + b1) * s1 + t1, 0.f) + g1;
                v2 = fmaxf((v2 + b0) * s0 + t0, 0.f) + g0;
                v3 = fmaxf((v3 + b1) * s1 + t1, 0.f) + g1;
                if (row0 < N)     *(float2*)(g_y + (size_t)row0 * 128 + col) = make_float2(v0, v1);
                if (row0 + 8 < N) *(float2*)(g_y + (size_t)(row0 + 8) * 128 + col) = make_float2(v2, v3);
            }
        }
    }
}

// ---------------- single-pass flash-style softmax + aggregation (warp per node) ----------
// OUTMODE 0: write split bf16 (g_ah/g_al, K=128).  OUTMODE 1: fused classifier -> out.
template <int OUTMODE>
__global__ void agg_k(int N, const float* __restrict__ cw, const float* __restrict__ cb,
                      float* __restrict__ out)
{
    int n = (blockIdx.x * blockDim.x + threadIdx.x) >> 5;
    int lane = threadIdx.x & 31;
    if (n >= N) return;
    int head = lane >> 3;
    float myald = comp4(((const float4*)g_ald)[n], head);
    float eself = lrelu(comp4(((const float4*)g_als)[n], head) + myald);

    const float4* h4 = (const float4*)g_h;

    float m = eself, s = 1.f;
    float4 acc = h4[(size_t)n * 32 + lane];

    int beg = g_rowptr[n], end = g_rowptr[n + 1];
    int i = beg;
    for (; i + 4 <= end; i += 4) {
        int s0 = g_csr[i], s1 = g_csr[i + 1], s2 = g_csr[i + 2], s3 = g_csr[i + 3];
        float4 hv0 = h4[(size_t)s0 * 32 + lane];
        float4 hv1 = h4[(size_t)s1 * 32 + lane];
        float4 hv2 = h4[(size_t)s2 * 32 + lane];
        float4 hv3 = h4[(size_t)s3 * 32 + lane];
        float e0 = lrelu(g_als[s0 * 4 + head] + myald);
        float e1 = lrelu(g_als[s1 * 4 + head] + myald);
        float e2 = lrelu(g_als[s2 * 4 + head] + myald);
        float e3 = lrelu(g_als[s3 * 4 + head] + myald);
        float mx = fmaxf(fmaxf(e0, e1), fmaxf(e2, e3));
        if (mx > m) {
            float r = __expf(m - mx);
            s *= r;
            acc.x *= r; acc.y *= r; acc.z *= r; acc.w *= r;
            m = mx;
        }
        float p0 = __expf(e0 - m), p1 = __expf(e1 - m);
        float p2 = __expf(e2 - m), p3 = __expf(e3 - m);
        s += p0 + p1 + p2 + p3;
        acc.x += p0 * hv0.x + p1 * hv1.x + p2 * hv2.x + p3 * hv3.x;
        acc.y += p0 * hv0.y + p1 * hv1.y + p2 * hv2.y + p3 * hv3.y;
        acc.z += p0 * hv0.z + p1 * hv1.z + p2 * hv2.z + p3 * hv3.z;
        acc.w += p0 * hv0.w + p1 * hv1.w + p2 * hv2.w + p3 * hv3.w;
    }
    for (; i < end; i++) {
        int si = g_csr[i];
        float4 hv = h4[(size_t)si * 32 + lane];
        float e = lrelu(g_als[si * 4 + head] + myald);
        if (e > m) {
            float r = __expf(m - e);
            s *= r;
            acc.x *= r; acc.y *= r; acc.z *= r; acc.w *= r;
            m = e;
        }
        float p = __expf(e - m);
        s += p;
        acc.x += p * hv.x; acc.y += p * hv.y;
        acc.z += p * hv.z; acc.w += p * hv.w;
    }

    float inv = 1.f / s;
    float4 yv = ((const float4*)g_y)[(size_t)n * 32 + lane];
    float4 o4;
    o4.x = fmaxf(acc.x * inv + yv.x, 0.f);
    o4.y = fmaxf(acc.y * inv + yv.y, 0.f);
    o4.z = fmaxf(acc.z * inv + yv.z, 0.f);
    o4.w = fmaxf(acc.w * inv + yv.w, 0.f);

    if (OUTMODE == 0) {
        float r0, r1, r2, r3;
        uint32_t h0 = split_pack(o4.x, o4.y, r0, r1);
        uint32_t h1 = split_pack(o4.z, o4.w, r2, r3);
        ((uint2*)g_ah)[(size_t)n * 32 + lane] = make_uint2(h0, h1);
        ((uint2*)g_al)[(size_t)n * 32 + lane] = make_uint2(pack_bf(r0, r1), pack_bf(r2, r3));
    } else {
        int k0 = lane * 4;
#pragma unroll
        for (int o = 0; o < 10; o++) {
            float p = o4.x * cw[(k0 + 0) * 10 + o] + o4.y * cw[(k0 + 1) * 10 + o]
                    + o4.z * cw[(k0 + 2) * 10 + o] + o4.w * cw[(k0 + 3) * 10 + o];
#pragma unroll
            for (int off = 16; off; off >>= 1) p += __shfl_xor_sync(0xffffffffu, p, off);
            if (lane == 0) out[(size_t)n * 10 + o] = p + cb[o];
        }
    }
}

// ---------------- host ----------------
static const int TCF_SMEM = NSTAGE * STG_B;   // 184320 bytes

struct HxStreams {
    cudaStream_t s2 = 0;
    cudaEvent_t e1 = 0, e2 = 0, e3 = 0;
    bool ok = false;
    HxStreams() {
        ok = (cudaStreamCreateWithFlags(&s2, cudaStreamNonBlocking) == cudaSuccess)
          && (cudaEventCreateWithFlags(&e1, cudaEventDisableTiming) == cudaSuccess)
          && (cudaEventCreateWithFlags(&e2, cudaEventDisableTiming) == cudaSuccess)
          && (cudaEventCreateWithFlags(&e3, cudaEventDisableTiming) == cudaSuccess);
    }
};
static HxStreams hx;

extern "C" void kernel_launch(void* const* d_in, const int* in_sizes, int n_in,
                              void* d_out, int out_size)
{
    const float* x = (const float*)d_in[0];
    const int* ei = (const int*)d_in[1];
    int N = in_sizes[0] / 512;
    int E = in_sizes[1] / 2;
    const int* src = ei;
    const int* dst = ei + E;

    const float* gw[3]    = {(const float*)d_in[3],  (const float*)d_in[11], (const float*)d_in[19]};
    const float* gas[3]   = {(const float*)d_in[4],  (const float*)d_in[12], (const float*)d_in[20]};
    const float* gad[3]   = {(const float*)d_in[5],  (const float*)d_in[13], (const float*)d_in[21]};
    const float* gbp[3]   = {(const float*)d_in[6],  (const float*)d_in[14], (const float*)d_in[22]};
    const float* fw[3]    = {(const float*)d_in[7],  (const float*)d_in[15], (const float*)d_in[23]};
    const float* fbp[3]   = {(const float*)d_in[8],  (const float*)d_in[16], (const float*)d_in[24]};
    const float* fgp[3]   = {(const float*)d_in[9],  (const float*)d_in[17], (const float*)d_in[25]};
    const float* fbeta[3] = {(const float*)d_in[10], (const float*)d_in[18], (const float*)d_in[26]};
    const float* cw = (const float*)d_in[27];
    const float* cb = (const float*)d_in[28];

    cudaFuncSetAttribute(tcfused_k, cudaFuncAttributeMaxDynamicSharedMemorySize, TCF_SMEM);

    int nb = (N + 1023) / 1024;
    int gemmBlocks = (N + 127) / 128;
    int warpBlocks = (N * 32 + 255) / 256;

    bool fork = hx.ok;
    cudaStream_t sB = fork ? hx.s2 : (cudaStream_t)0;

    if (fork) {
        cudaEventRecord(hx.e1, 0);
        cudaStreamWaitEvent(hx.s2, hx.e1, 0);
    }

    // side stream: layer-0 weight prep FIRST (overlaps asplit), then CSR + l1/l2 prep
    wprep2_k<<<dim3(256, 2), 256, 0, sB>>>(gw[0], fw[0], 512, 0);
    if (fork) cudaEventRecord(hx.e3, hx.s2);
    zero_deg_k<<<(N + 255) / 256, 256, 0, sB>>>(N);
    hist_k<<<(E + 255) / 256, 256, 0, sB>>>(dst, E, N);
    scan1_k<<<nb, 1024, 0, sB>>>(N);
    scan2_k<<<1, 256, 0, sB>>>(nb);
    scan3_k<<<nb, 1024, 0, sB>>>(N, E);
    scatter_k<<<(E + 255) / 256, 256, 0, sB>>>(src, dst, E, N);
    wprep2_k<<<dim3(64, 2), 256, 0, sB>>>(gw[1], fw[1], 128, 2);
    wprep2_k<<<dim3(64, 2), 256, 0, sB>>>(gw[2], fw[2], 128, 4);

    // main stream: input split (overlaps wprep0), then layer-0 fused GEMM
    asplit_k<<<(N * 512 / 4 + 255) / 256, 256>>>(x, N * 512 / 4);
    if (fork) cudaStreamWaitEvent(0, hx.e3, 0);
    tcfused_k<<<gemmBlocks, 512, TCF_SMEM>>>(0, 512, N, gas[0], gad[0], fbp[0], fgp[0], fbeta[0], gbp[0]);

    if (fork) {
        cudaEventRecord(hx.e2, hx.s2);
        cudaStreamWaitEvent(0, hx.e2, 0);
    }

    // layer 0 aggregation -> split activations for layer 1
    agg_k<0><<<warpBlocks, 256>>>(N, nullptr, nullptr, nullptr);

    // layer 1 (K=128)
    tcfused_k<<<gemmBlocks, 512, TCF_SMEM>>>(2, 128, N, gas[1], gad[1], fbp[1], fgp[1], fbeta[1], gbp[1]);
    agg_k<0><<<warpBlocks, 256>>>(N, nullptr, nullptr, nullptr);

    // layer 2 (K=128), final agg fuses the classifier
    tcfused_k<<<gemmBlocks, 512, TCF_SMEM>>>(4, 128, N, gas[2], gad[2], fbp[2], fgp[2], fbeta[2], gbp[2]);
    agg_k<1><<<warpBlocks, 256>>>(N, cw, cb, (float*)d_out);
}